// round 4
// baseline (speedup 1.0000x reference)
#include <cuda_runtime.h>
#include <cuda_bf16.h>
#include <math.h>
#include <stdint.h>

#define NROWS 32768      // B*S
#define FFN   2048
#define EMB   512

// ---------------- scratch ---------------------------------------------------
__device__ float         g_EV[NROWS * 8];        // 1 MB
__device__ __nv_bfloat16 g_Wh[EMB * FFN];        // 2 MB
__device__ __nv_bfloat16 g_Wl[EMB * FFN];        // 2 MB

// ---------------------------------------------------------------------------
// Kernel 1: quantum circuit collapsed to closed form (verified R1/R2).
// ---------------------------------------------------------------------------
__global__ void ev_kernel(const float* __restrict__ x,
                          const float* __restrict__ params) {
    int row = blockIdx.x * blockDim.x + threadIdx.x;
    if (row >= NROWS) return;
    float z[8];
#pragma unroll
    for (int i = 0; i < 8; i++) {
        float a = params[i * 3 + 0];
        float b = params[i * 3 + 1];
        float c = params[i * 3 + 2];
        float sa, ca, sb, cb, sc, cc;
        sincosf(a, &sa, &ca);
        sincosf(b, &sb, &cb);
        sincosf(c, &sc, &cc);
        float Acoef = ca * cc + sa * sb * sc;
        float Ccoef = cb * sc;
        float sx, cx;
        sincosf(x[row * 8 + i], &sx, &cx);
        z[i] = Acoef * cx - Ccoef * sx;
    }
    float ev[8];
    float pre = z[0];
#pragma unroll
    for (int k = 1; k < 8; k++) { pre *= z[k]; ev[k] = pre; }
    float suf = 1.0f;
#pragma unroll
    for (int k = 7; k >= 1; k--) suf *= z[k];
    ev[0] = suf;
    float4* out = (float4*)&g_EV[row * 8];
    out[0] = make_float4(ev[0], ev[1], ev[2], ev[3]);
    out[1] = make_float4(ev[4], ev[5], ev[6], ev[7]);
}

// ---------------------------------------------------------------------------
// Kernel 2: split W2 [EMB, FFN] into bf16 hi/lo
// ---------------------------------------------------------------------------
__global__ void w_split_kernel(const float* __restrict__ W2) {
    int idx = blockIdx.x * blockDim.x + threadIdx.x;   // [0, EMB*FFN/2)
    float2 v = ((const float2*)W2)[idx];
    __nv_bfloat16 h0 = __float2bfloat16(v.x);
    __nv_bfloat16 h1 = __float2bfloat16(v.y);
    __nv_bfloat16 l0 = __float2bfloat16(v.x - __bfloat162float(h0));
    __nv_bfloat16 l1 = __float2bfloat16(v.y - __bfloat162float(h1));
    ((__nv_bfloat162*)g_Wh)[idx] = __halves2bfloat162(h0, h1);
    ((__nv_bfloat162*)g_Wl)[idx] = __halves2bfloat162(l0, l1);
}

// ---------------------------------------------------------------------------
// Kernel 3 (fused): OUT = relu(EV@W1^T + b1) @ W2^T + b2
// H generated in-kernel (rank-8), split bf16 hi/lo, 3-pass mma.sync bf16.
// BM=64, BN=256, BK=32, 512 threads (16 warps, warp tile 16x64).
// H double-buffered (STS), B triple-buffered (cp.async). 112 KB smem.
// ---------------------------------------------------------------------------
#define BM 64
#define BN 256
#define BK 32
#define NT (FFN / BK)                 // 64
#define HT_B 4096                     // 64 x 32 bf16 (one of hi/lo)
#define BT_B 16384                    // 256 x 32 bf16 (one of hi/lo)
#define SM_H 0                        // 2 stages x (hi+lo) = 16 KB
#define SM_B (2 * 2 * HT_B)           // 3 stages x (hi+lo) = 96 KB
#define SMEM_TOTAL (SM_B + 3 * 2 * BT_B)   // 114688

#define CP16(dst, src) \
    asm volatile("cp.async.cg.shared.global [%0], [%1], 16;\n" :: "r"(dst), "l"(src))

__device__ __forceinline__ void ldsm4(unsigned* r, unsigned a) {
    asm volatile("ldmatrix.sync.aligned.m8n8.x4.shared.b16 {%0,%1,%2,%3}, [%4];"
                 : "=r"(r[0]), "=r"(r[1]), "=r"(r[2]), "=r"(r[3]) : "r"(a));
}

__device__ __forceinline__ void mma16816(float* c, const unsigned* a, const unsigned* b) {
    asm volatile("mma.sync.aligned.m16n8k16.row.col.f32.bf16.bf16.f32 "
                 "{%0,%1,%2,%3}, {%4,%5,%6,%7}, {%8,%9}, {%0,%1,%2,%3};"
                 : "+f"(c[0]), "+f"(c[1]), "+f"(c[2]), "+f"(c[3])
                 : "r"(a[0]), "r"(a[1]), "r"(a[2]), "r"(a[3]), "r"(b[0]), "r"(b[1]));
}

__device__ __forceinline__ unsigned swz(int row, int ch) {  // 64B rows, 16B chunks
    return (unsigned)(row * 64 + ((ch ^ ((row >> 1) & 3)) << 4));
}

// B-stage loader: 4 chunks/thread each for Wh and Wl
__device__ __forceinline__ void load_B(uint32_t st, int bn, int tid, int k0) {
#pragma unroll
    for (int i = 0; i < 2; i++) {
        int id = tid + (i << 9);          // 0..1023
        int r  = id >> 2;                 // 0..255
        int c  = id & 3;                  // 16B chunk 0..3
        unsigned so = swz(r, c);
        size_t g = (size_t)(bn + r) * FFN + k0 + c * 8;
        CP16(st + so,        g_Wh + g);
        CP16(st + BT_B + so, g_Wl + g);
    }
}

// H-tile generator: thread t handles row (t>>3), ks (t&7)*4 .. +3
__device__ __forceinline__ void hgen(uint32_t dst, int k0, int tid,
                                     float4 e0, float4 e1,
                                     const float* __restrict__ W1,
                                     const float* __restrict__ b1) {
    int r  = tid >> 3;
    int kq = (tid & 7) << 2;
    float4 bv = *(const float4*)&b1[k0 + kq];
    float hb[4] = {bv.x, bv.y, bv.z, bv.w};
    __align__(8) __nv_bfloat16 hi4[4];
    __align__(8) __nv_bfloat16 lo4[4];
#pragma unroll
    for (int j = 0; j < 4; j++) {
        int k = k0 + kq + j;
        float4 w0 = *(const float4*)&W1[k * 8];
        float4 w1 = *(const float4*)&W1[k * 8 + 4];
        float h = hb[j]
                + e0.x * w0.x + e0.y * w0.y + e0.z * w0.z + e0.w * w0.w
                + e1.x * w1.x + e1.y * w1.y + e1.z * w1.z + e1.w * w1.w;
        h = fmaxf(h, 0.0f);
        __nv_bfloat16 hi = __float2bfloat16(h);
        hi4[j] = hi;
        lo4[j] = __float2bfloat16(h - __bfloat162float(hi));
    }
    unsigned so = swz(r, (tid & 7) >> 1) + ((tid & 1) << 3);
    const unsigned* hp = (const unsigned*)hi4;
    const unsigned* lp = (const unsigned*)lo4;
    asm volatile("st.shared.v2.u32 [%0], {%1,%2};"
                 :: "r"(dst + so), "r"(hp[0]), "r"(hp[1]));
    asm volatile("st.shared.v2.u32 [%0], {%1,%2};"
                 :: "r"(dst + HT_B + so), "r"(lp[0]), "r"(lp[1]));
}

__global__ void __launch_bounds__(512, 1)
fused_gemm(const float* __restrict__ W1, const float* __restrict__ b1,
           const float* __restrict__ bias, float* __restrict__ C) {
    extern __shared__ __align__(128) unsigned char smem[];
    uint32_t sb;
    asm("{ .reg .u64 t; cvta.to.shared.u64 t, %1; cvt.u32.u64 %0, t; }"
        : "=r"(sb) : "l"(smem));

    const int tid  = threadIdx.x;
    const int w    = tid >> 5;            // 0..15
    const int lane = tid & 31;
    const int wm = w & 3;                 // 4 m-groups of 16 rows
    const int wn = w >> 2;                // 4 n-groups of 64 cols
    const int bm = blockIdx.y * BM;
    const int bn = blockIdx.x * BN;

    // EV row for this thread's hgen duty
    const float4* evp = (const float4*)&g_EV[(size_t)(bm + (tid >> 3)) * 8];
    float4 e0 = evp[0], e1 = evp[1];

    float acc[8][4];
#pragma unroll
    for (int i = 0; i < 8; i++)
#pragma unroll
        for (int j = 0; j < 4; j++) acc[i][j] = 0.0f;

    // prologue: H(0), B(0), B(1)
    hgen(sb + SM_H, 0, tid, e0, e1, W1, b1);
    load_B(sb + SM_B, bn, tid, 0);
    asm volatile("cp.async.commit_group;\n");
    load_B(sb + SM_B + 2 * BT_B, bn, tid, BK);
    asm volatile("cp.async.commit_group;\n");

    for (int t = 0; t < NT; t++) {
        if (t == NT - 1) asm volatile("cp.async.wait_group 0;\n" ::: "memory");
        else             asm volatile("cp.async.wait_group 1;\n" ::: "memory");
        __syncthreads();

        uint32_t hs = sb + SM_H + (t & 1) * (2 * HT_B);
        uint32_t bs = sb + SM_B + (t % 3) * (2 * BT_B);

#pragma unroll
        for (int kk = 0; kk < 2; kk++) {
            unsigned ah[4], al[4], bh[4][4], bl[4][4];
            {   // A frag: m16 x k16
                int r  = wm * 16 + (lane & 15);
                int ch = kk * 2 + (lane >> 4);
                unsigned a = hs + swz(r, ch);
                ldsm4(ah, a);
                ldsm4(al, a + HT_B);
            }
#pragma unroll
            for (int nb = 0; nb < 4; nb++) {   // B frags: 64 cols
                int n  = wn * 64 + nb * 16 + (lane & 7) + ((lane >> 4) & 1) * 8;
                int ch = kk * 2 + ((lane >> 3) & 1);
                unsigned a = bs + swz(n, ch);
                ldsm4(bh[nb], a);
                ldsm4(bl[nb], a + BT_B);
            }
#pragma unroll
            for (int nf = 0; nf < 8; nf++) {
                const unsigned* bhp = &bh[nf >> 1][(nf & 1) * 2];
                const unsigned* blp = &bl[nf >> 1][(nf & 1) * 2];
                mma16816(acc[nf], ah, bhp);   // Ah*Bh
                mma16816(acc[nf], al, bhp);   // Al*Bh
                mma16816(acc[nf], ah, blp);   // Ah*Bl
            }
        }

        if (t + 1 < NT)
            hgen(sb + SM_H + ((t + 1) & 1) * (2 * HT_B), (t + 1) * BK,
                 tid, e0, e1, W1, b1);
        if (t + 2 < NT) {
            load_B(sb + SM_B + ((t + 2) % 3) * (2 * BT_B), bn, tid, (t + 2) * BK);
            asm volatile("cp.async.commit_group;\n");
        }
    }

    // epilogue
#pragma unroll
    for (int nf = 0; nf < 8; nf++) {
        int cc = bn + wn * 64 + nf * 8 + (lane & 3) * 2;
        float2 b2 = *(const float2*)&bias[cc];
        int r0 = bm + wm * 16 + (lane >> 2);
        float2 v0 = make_float2(acc[nf][0] + b2.x, acc[nf][1] + b2.y);
        float2 v1 = make_float2(acc[nf][2] + b2.x, acc[nf][3] + b2.y);
        *(float2*)&C[(size_t)r0 * EMB + cc]       = v0;
        *(float2*)&C[(size_t)(r0 + 8) * EMB + cc] = v1;
    }
}

// ---------------------------------------------------------------------------
extern "C" void kernel_launch(void* const* d_in, const int* in_sizes, int n_in,
                              void* d_out, int out_size) {
    const float* x      = (const float*)d_in[0];  // [16,2048,8]
    const float* params = (const float*)d_in[1];  // [8,3]
    const float* W1     = (const float*)d_in[2];  // [2048,8]
    const float* b1     = (const float*)d_in[3];  // [2048]
    const float* W2     = (const float*)d_in[4];  // [512,2048]
    const float* b2     = (const float*)d_in[5];  // [512]
    float* out = (float*)d_out;                   // [16,2048,512]

    // idempotent, deterministic, non-allocating; needed for 112 KB dyn smem
    cudaFuncSetAttribute(fused_gemm, cudaFuncAttributeMaxDynamicSharedMemorySize,
                         SMEM_TOTAL);

    ev_kernel<<<NROWS / 256, 256>>>(x, params);
    w_split_kernel<<<(EMB * (FFN / 2)) / 256, 256>>>(W2);
    fused_gemm<<<dim3(EMB / BN, NROWS / BM), 512, SMEM_TOTAL>>>(W1, b1, b2, out);
}

// round 5
// speedup vs baseline: 1.7044x; 1.7044x over previous
#include <cuda_runtime.h>
#include <cuda_fp16.h>
#include <math.h>
#include <stdint.h>

#define NROWS 32768      // B*S
#define FFN   2048
#define EMB   512

// ---------------- scratch ---------------------------------------------------
__device__ float  g_EV[NROWS * 8];                 // 1 MB
__device__ __half g_H[(size_t)NROWS * FFN];        // 128 MB (fp16 hi of H)
__device__ __half g_Wh[EMB * FFN];                 // 2 MB  (fp16 hi of 1024*W2)
__device__ __half g_Wl[EMB * FFN];                 // 2 MB  (fp16 lo of 1024*W2)

// ---------------------------------------------------------------------------
// Kernel 1: quantum circuit collapsed to closed form (verified R1/R2).
// ---------------------------------------------------------------------------
__global__ void ev_kernel(const float* __restrict__ x,
                          const float* __restrict__ params) {
    int row = blockIdx.x * blockDim.x + threadIdx.x;
    if (row >= NROWS) return;
    float z[8];
#pragma unroll
    for (int i = 0; i < 8; i++) {
        float a = params[i * 3 + 0];
        float b = params[i * 3 + 1];
        float c = params[i * 3 + 2];
        float sa, ca, sb, cb, sc, cc;
        sincosf(a, &sa, &ca);
        sincosf(b, &sb, &cb);
        sincosf(c, &sc, &cc);
        float Acoef = ca * cc + sa * sb * sc;
        float Ccoef = cb * sc;
        float sx, cx;
        sincosf(x[row * 8 + i], &sx, &cx);
        z[i] = Acoef * cx - Ccoef * sx;
    }
    float ev[8];
    float pre = z[0];
#pragma unroll
    for (int k = 1; k < 8; k++) { pre *= z[k]; ev[k] = pre; }
    float suf = 1.0f;
#pragma unroll
    for (int k = 7; k >= 1; k--) suf *= z[k];
    ev[0] = suf;
    float4* out = (float4*)&g_EV[row * 8];
    out[0] = make_float4(ev[0], ev[1], ev[2], ev[3]);
    out[1] = make_float4(ev[4], ev[5], ev[6], ev[7]);
}

// ---------------------------------------------------------------------------
// Kernel 2: H = relu(EV @ W1^T + b1) -> fp16, 8 cols/thread, one uint4 store
// ---------------------------------------------------------------------------
__global__ void h_half_kernel(const float* __restrict__ W1,
                              const float* __restrict__ b1) {
    int idx = blockIdx.x * blockDim.x + threadIdx.x;   // [0, NROWS*256)
    int row = idx >> 8;
    int c0  = (idx & 255) << 3;
    const float4* e = (const float4*)&g_EV[row * 8];
    float4 e0 = e[0], e1 = e[1];
    __align__(16) __half hv[8];
#pragma unroll
    for (int j = 0; j < 8; j++) {
        const float4* w = (const float4*)&W1[(c0 + j) * 8];
        float4 w0 = w[0], w1 = w[1];
        float h = b1[c0 + j]
                + e0.x * w0.x + e0.y * w0.y + e0.z * w0.z + e0.w * w0.w
                + e1.x * w1.x + e1.y * w1.y + e1.z * w1.z + e1.w * w1.w;
        hv[j] = __float2half(fmaxf(h, 0.0f));
    }
    *(uint4*)&g_H[(size_t)idx * 8] = *(const uint4*)hv;
}

// ---------------------------------------------------------------------------
// Kernel 3: split 1024*W2 into fp16 hi/lo (scaling keeps lo out of denormals)
// ---------------------------------------------------------------------------
__global__ void w_split_kernel(const float* __restrict__ W2) {
    int idx = blockIdx.x * blockDim.x + threadIdx.x;   // [0, EMB*FFN/2)
    float2 v = ((const float2*)W2)[idx];
    float v0 = v.x * 1024.0f, v1 = v.y * 1024.0f;
    __half h0 = __float2half(v0);
    __half h1 = __float2half(v1);
    __half l0 = __float2half(v0 - __half2float(h0));
    __half l1 = __float2half(v1 - __half2float(h1));
    ((__half2*)g_Wh)[idx] = __halves2half2(h0, h1);
    ((__half2*)g_Wl)[idx] = __halves2half2(l0, l1);
}

// ---------------------------------------------------------------------------
// Kernel 4: OUT = H @ W2^T + b2 via mma.sync fp16, 2-pass (Ah*Bh + Ah*Bl)
// CTA 128x64x32, 8 warps (4x2, warp tile 32x32), 3-stage cp.async pipeline,
// XOR-swizzled smem, 48KB static smem, 2 CTAs/SM.  (R2-proven skeleton.)
// ---------------------------------------------------------------------------
#define BM 128
#define BN 64
#define BK 32
#define NT (FFN / BK)             // 64
// stage layout (bytes): A 0 (8192), Bh 8192 (4096), Bl 12288 (4096)
#define STG 16384

#define CP16(dst, src) \
    asm volatile("cp.async.cg.shared.global [%0], [%1], 16;\n" :: "r"(dst), "l"(src))

__device__ __forceinline__ void ldsm4(unsigned* r, unsigned a) {
    asm volatile("ldmatrix.sync.aligned.m8n8.x4.shared.b16 {%0,%1,%2,%3}, [%4];"
                 : "=r"(r[0]), "=r"(r[1]), "=r"(r[2]), "=r"(r[3]) : "r"(a));
}

__device__ __forceinline__ void mma16816(float* c, const unsigned* a, const unsigned* b) {
    asm volatile("mma.sync.aligned.m16n8k16.row.col.f32.f16.f16.f32 "
                 "{%0,%1,%2,%3}, {%4,%5,%6,%7}, {%8,%9}, {%0,%1,%2,%3};"
                 : "+f"(c[0]), "+f"(c[1]), "+f"(c[2]), "+f"(c[3])
                 : "r"(a[0]), "r"(a[1]), "r"(a[2]), "r"(a[3]), "r"(b[0]), "r"(b[1]));
}

__device__ __forceinline__ unsigned swz(int row, int ch) {  // 64B rows, 16B chunks
    return (unsigned)(row * 64 + ((ch ^ ((row >> 1) & 3)) << 4));
}

__device__ __forceinline__ void load_stage(unsigned st, int bm, int bn, int tid, int k0) {
#pragma unroll
    for (int i = 0; i < 2; i++) {               // A: 512 chunks of 16B
        int id = tid + (i << 8);
        int r = id >> 2, c = id & 3;
        size_t g = (size_t)(bm + r) * FFN + k0 + c * 8;
        CP16(st + swz(r, c), g_H + g);
    }
    {                                           // B: 256 chunks each hi/lo
        int r = tid >> 2, c = tid & 3;
        unsigned so = swz(r, c);
        size_t g = (size_t)(bn + r) * FFN + k0 + c * 8;
        CP16(st + 8192 + so,  g_Wh + g);
        CP16(st + 12288 + so, g_Wl + g);
    }
}

__global__ void __launch_bounds__(256, 2)
mma_gemm(const float* __restrict__ bias, float* __restrict__ C) {
    __shared__ __align__(128) unsigned char smem[3 * STG];
    const int tid  = threadIdx.x;
    const int warp = tid >> 5, lane = tid & 31;
    const int wm = warp & 3, wn = warp >> 2;
    const int bm = blockIdx.y * BM, bn = blockIdx.x * BN;
    const unsigned sbase = (unsigned)__cvta_generic_to_shared(smem);

    float acc[2][4][4];
#pragma unroll
    for (int i = 0; i < 2; i++)
#pragma unroll
        for (int j = 0; j < 4; j++)
#pragma unroll
            for (int k = 0; k < 4; k++) acc[i][j][k] = 0.0f;

    load_stage(sbase,       bm, bn, tid, 0);
    asm volatile("cp.async.commit_group;\n");
    load_stage(sbase + STG, bm, bn, tid, BK);
    asm volatile("cp.async.commit_group;\n");

    for (int t = 0; t < NT; t++) {
        if (t + 1 < NT) asm volatile("cp.async.wait_group 1;\n" ::: "memory");
        else            asm volatile("cp.async.wait_group 0;\n" ::: "memory");
        __syncthreads();

        // issue load for t+2 into buffer (t+2)%3 (freed by t-1's consumers)
        if (t + 2 < NT) {
            load_stage(sbase + ((t + 2) % 3) * STG, bm, bn, tid, (t + 2) * BK);
            asm volatile("cp.async.commit_group;\n");
        }

        unsigned st = sbase + (t % 3) * STG;
#pragma unroll
        for (int kk = 0; kk < 2; kk++) {
            unsigned ah[2][4], bh[2][4], bl[2][4];
#pragma unroll
            for (int mf = 0; mf < 2; mf++) {     // A fragments (16x16)
                int r  = wm * 32 + mf * 16 + (lane & 15);
                int ch = kk * 2 + (lane >> 4);
                ldsm4(ah[mf], st + swz(r, ch));
            }
#pragma unroll
            for (int nb = 0; nb < 2; nb++) {     // B fragments
                int n  = wn * 32 + nb * 16 + (lane & 7) + ((lane >> 4) & 1) * 8;
                int ch = kk * 2 + ((lane >> 3) & 1);
                unsigned a = st + 8192 + swz(n, ch);
                ldsm4(bh[nb], a);
                ldsm4(bl[nb], a + 4096);
            }
#pragma unroll
            for (int mf = 0; mf < 2; mf++)
#pragma unroll
                for (int nf = 0; nf < 4; nf++) {
                    const unsigned* bhp = &bh[nf >> 1][(nf & 1) * 2];
                    const unsigned* blp = &bl[nf >> 1][(nf & 1) * 2];
                    mma16816(acc[mf][nf], ah[mf], bhp);   // Ah*Bh
                    mma16816(acc[mf][nf], ah[mf], blp);   // Ah*Bl
                }
        }
        __syncthreads();
    }

    // epilogue: undo the 1024x W2 scaling, add bias
    const float inv = 1.0f / 1024.0f;
#pragma unroll
    for (int mf = 0; mf < 2; mf++) {
        int r0 = bm + wm * 32 + mf * 16 + (lane >> 2);
#pragma unroll
        for (int nf = 0; nf < 4; nf++) {
            int cc = bn + wn * 32 + nf * 8 + (lane & 3) * 2;
            float2 b2 = *(const float2*)&bias[cc];
            float2 v0 = make_float2(acc[mf][nf][0] * inv + b2.x,
                                    acc[mf][nf][1] * inv + b2.y);
            float2 v1 = make_float2(acc[mf][nf][2] * inv + b2.x,
                                    acc[mf][nf][3] * inv + b2.y);
            *(float2*)&C[(size_t)r0 * EMB + cc]       = v0;
            *(float2*)&C[(size_t)(r0 + 8) * EMB + cc] = v1;
        }
    }
}

// ---------------------------------------------------------------------------
extern "C" void kernel_launch(void* const* d_in, const int* in_sizes, int n_in,
                              void* d_out, int out_size) {
    const float* x      = (const float*)d_in[0];  // [16,2048,8]
    const float* params = (const float*)d_in[1];  // [8,3]
    const float* W1     = (const float*)d_in[2];  // [2048,8]
    const float* b1     = (const float*)d_in[3];  // [2048]
    const float* W2     = (const float*)d_in[4];  // [512,2048]
    const float* b2     = (const float*)d_in[5];  // [512]
    float* out = (float*)d_out;                   // [16,2048,512]

    ev_kernel<<<NROWS / 256, 256>>>(x, params);
    h_half_kernel<<<(NROWS * 256) / 256, 256>>>(W1, b1);
    w_split_kernel<<<(EMB * (FFN / 2)) / 256, 256>>>(W2);
    mma_gemm<<<dim3(EMB / BN, NROWS / BM), 256>>>(b2, out);
}

// round 6
// speedup vs baseline: 3.5297x; 2.0710x over previous
#include <cuda_runtime.h>
#include <cuda_fp16.h>
#include <math.h>
#include <stdint.h>

#define NROWS 32768      // B*S
#define FFN   2048
#define EMB   512

// ---------------- scratch ---------------------------------------------------
__device__ float  g_EV[NROWS * 8];                 // 1 MB
__device__ __half g_H[(size_t)NROWS * FFN];        // 128 MB (fp16 of H)
__device__ __half g_Wh[EMB * FFN];                 // 2 MB  (fp16 hi of 1024*W2)
__device__ __half g_Wl[EMB * FFN];                 // 2 MB  (fp16 lo of 1024*W2)

// ---------------------------------------------------------------------------
// Kernel 1: quantum circuit collapsed to closed form (verified R1/R2).
// ---------------------------------------------------------------------------
__global__ void ev_kernel(const float* __restrict__ x,
                          const float* __restrict__ params) {
    int row = blockIdx.x * blockDim.x + threadIdx.x;
    if (row >= NROWS) return;
    float z[8];
#pragma unroll
    for (int i = 0; i < 8; i++) {
        float a = params[i * 3 + 0];
        float b = params[i * 3 + 1];
        float c = params[i * 3 + 2];
        float sa, ca, sb, cb, sc, cc;
        sincosf(a, &sa, &ca);
        sincosf(b, &sb, &cb);
        sincosf(c, &sc, &cc);
        float Acoef = ca * cc + sa * sb * sc;
        float Ccoef = cb * sc;
        float sx, cx;
        sincosf(x[row * 8 + i], &sx, &cx);
        z[i] = Acoef * cx - Ccoef * sx;
    }
    float ev[8];
    float pre = z[0];
#pragma unroll
    for (int k = 1; k < 8; k++) { pre *= z[k]; ev[k] = pre; }
    float suf = 1.0f;
#pragma unroll
    for (int k = 7; k >= 1; k--) suf *= z[k];
    ev[0] = suf;
    float4* out = (float4*)&g_EV[row * 8];
    out[0] = make_float4(ev[0], ev[1], ev[2], ev[3]);
    out[1] = make_float4(ev[4], ev[5], ev[6], ev[7]);
}

// ---------------------------------------------------------------------------
// Kernel 2 (v2): H = relu(EV @ W1^T + b1) -> fp16.
// Thread owns 2 columns (W1 cached in 16 regs), loops over 64 rows.
// Per row: 2 warp-broadcast float4 EV loads + 1 coalesced half2 store.
// ---------------------------------------------------------------------------
#define HROWS 64
__global__ void __launch_bounds__(256)
h_half_kernel(const float* __restrict__ W1, const float* __restrict__ b1) {
    int c0 = blockIdx.x * 512 + threadIdx.x * 2;   // two columns c0, c0+1
    int r0 = blockIdx.y * HROWS;
    float4 wa0 = *(const float4*)&W1[c0 * 8];
    float4 wa1 = *(const float4*)&W1[c0 * 8 + 4];
    float4 wb0 = *(const float4*)&W1[(c0 + 1) * 8];
    float4 wb1 = *(const float4*)&W1[(c0 + 1) * 8 + 4];
    float ba = b1[c0], bb = b1[c0 + 1];
#pragma unroll 4
    for (int r = r0; r < r0 + HROWS; r++) {
        float4 e0 = *(const float4*)&g_EV[r * 8];
        float4 e1 = *(const float4*)&g_EV[r * 8 + 4];
        float ha = ba
                 + e0.x * wa0.x + e0.y * wa0.y + e0.z * wa0.z + e0.w * wa0.w
                 + e1.x * wa1.x + e1.y * wa1.y + e1.z * wa1.z + e1.w * wa1.w;
        float hb = bb
                 + e0.x * wb0.x + e0.y * wb0.y + e0.z * wb0.z + e0.w * wb0.w
                 + e1.x * wb1.x + e1.y * wb1.y + e1.z * wb1.z + e1.w * wb1.w;
        __half2 hv = __floats2half2_rn(fmaxf(ha, 0.0f), fmaxf(hb, 0.0f));
        *(__half2*)&g_H[(size_t)r * FFN + c0] = hv;
    }
}

// ---------------------------------------------------------------------------
// Kernel 3: split 1024*W2 into fp16 hi/lo (scaling keeps lo out of denormals)
// ---------------------------------------------------------------------------
__global__ void w_split_kernel(const float* __restrict__ W2) {
    int idx = blockIdx.x * blockDim.x + threadIdx.x;   // [0, EMB*FFN/2)
    float2 v = ((const float2*)W2)[idx];
    float v0 = v.x * 1024.0f, v1 = v.y * 1024.0f;
    __half h0 = __float2half(v0);
    __half h1 = __float2half(v1);
    __half l0 = __float2half(v0 - __half2float(h0));
    __half l1 = __float2half(v1 - __half2float(h1));
    ((__half2*)g_Wh)[idx] = __halves2half2(h0, h1);
    ((__half2*)g_Wl)[idx] = __halves2half2(l0, l1);
}

// ---------------------------------------------------------------------------
// Kernel 4: OUT = H @ W2^T + b2 via mma.sync fp16, 2-pass (Ah*Bh + Ah*Bl)
// CTA 128x64x32, 8 warps (4x2, warp tile 32x32), 3-stage cp.async pipeline,
// XOR-swizzled smem, 48KB static smem, 2 CTAs/SM.  (R5-proven, unchanged.)
// ---------------------------------------------------------------------------
#define BM 128
#define BN 64
#define BK 32
#define NT (FFN / BK)             // 64
#define STG 16384                 // A 0 (8192), Bh 8192 (4096), Bl 12288 (4096)

#define CP16(dst, src) \
    asm volatile("cp.async.cg.shared.global [%0], [%1], 16;\n" :: "r"(dst), "l"(src))

__device__ __forceinline__ void ldsm4(unsigned* r, unsigned a) {
    asm volatile("ldmatrix.sync.aligned.m8n8.x4.shared.b16 {%0,%1,%2,%3}, [%4];"
                 : "=r"(r[0]), "=r"(r[1]), "=r"(r[2]), "=r"(r[3]) : "r"(a));
}

__device__ __forceinline__ void mma16816(float* c, const unsigned* a, const unsigned* b) {
    asm volatile("mma.sync.aligned.m16n8k16.row.col.f32.f16.f16.f32 "
                 "{%0,%1,%2,%3}, {%4,%5,%6,%7}, {%8,%9}, {%0,%1,%2,%3};"
                 : "+f"(c[0]), "+f"(c[1]), "+f"(c[2]), "+f"(c[3])
                 : "r"(a[0]), "r"(a[1]), "r"(a[2]), "r"(a[3]), "r"(b[0]), "r"(b[1]));
}

__device__ __forceinline__ unsigned swz(int row, int ch) {  // 64B rows, 16B chunks
    return (unsigned)(row * 64 + ((ch ^ ((row >> 1) & 3)) << 4));
}

__device__ __forceinline__ void load_stage(unsigned st, int bm, int bn, int tid, int k0) {
#pragma unroll
    for (int i = 0; i < 2; i++) {               // A: 512 chunks of 16B
        int id = tid + (i << 8);
        int r = id >> 2, c = id & 3;
        size_t g = (size_t)(bm + r) * FFN + k0 + c * 8;
        CP16(st + swz(r, c), g_H + g);
    }
    {                                           // B: 256 chunks each hi/lo
        int r = tid >> 2, c = tid & 3;
        unsigned so = swz(r, c);
        size_t g = (size_t)(bn + r) * FFN + k0 + c * 8;
        CP16(st + 8192 + so,  g_Wh + g);
        CP16(st + 12288 + so, g_Wl + g);
    }
}

__global__ void __launch_bounds__(256, 2)
mma_gemm(const float* __restrict__ bias, float* __restrict__ C) {
    __shared__ __align__(128) unsigned char smem[3 * STG];
    const int tid  = threadIdx.x;
    const int warp = tid >> 5, lane = tid & 31;
    const int wm = warp & 3, wn = warp >> 2;
    const int bm = blockIdx.y * BM, bn = blockIdx.x * BN;
    const unsigned sbase = (unsigned)__cvta_generic_to_shared(smem);

    float acc[2][4][4];
#pragma unroll
    for (int i = 0; i < 2; i++)
#pragma unroll
        for (int j = 0; j < 4; j++)
#pragma unroll
            for (int k = 0; k < 4; k++) acc[i][j][k] = 0.0f;

    load_stage(sbase,       bm, bn, tid, 0);
    asm volatile("cp.async.commit_group;\n");
    load_stage(sbase + STG, bm, bn, tid, BK);
    asm volatile("cp.async.commit_group;\n");

    for (int t = 0; t < NT; t++) {
        if (t + 1 < NT) asm volatile("cp.async.wait_group 1;\n" ::: "memory");
        else            asm volatile("cp.async.wait_group 0;\n" ::: "memory");
        __syncthreads();

        if (t + 2 < NT) {
            load_stage(sbase + ((t + 2) % 3) * STG, bm, bn, tid, (t + 2) * BK);
            asm volatile("cp.async.commit_group;\n");
        }

        unsigned st = sbase + (t % 3) * STG;
#pragma unroll
        for (int kk = 0; kk < 2; kk++) {
            unsigned ah[2][4], bh[2][4], bl[2][4];
#pragma unroll
            for (int mf = 0; mf < 2; mf++) {     // A fragments (16x16)
                int r  = wm * 32 + mf * 16 + (lane & 15);
                int ch = kk * 2 + (lane >> 4);
                ldsm4(ah[mf], st + swz(r, ch));
            }
#pragma unroll
            for (int nb = 0; nb < 2; nb++) {     // B fragments
                int n  = wn * 32 + nb * 16 + (lane & 7) + ((lane >> 4) & 1) * 8;
                int ch = kk * 2 + ((lane >> 3) & 1);
                unsigned a = st + 8192 + swz(n, ch);
                ldsm4(bh[nb], a);
                ldsm4(bl[nb], a + 4096);
            }
#pragma unroll
            for (int mf = 0; mf < 2; mf++)
#pragma unroll
                for (int nf = 0; nf < 4; nf++) {
                    const unsigned* bhp = &bh[nf >> 1][(nf & 1) * 2];
                    const unsigned* blp = &bl[nf >> 1][(nf & 1) * 2];
                    mma16816(acc[mf][nf], ah[mf], bhp);   // Ah*Bh
                    mma16816(acc[mf][nf], ah[mf], blp);   // Ah*Bl
                }
        }
        __syncthreads();
    }

    // epilogue: undo the 1024x W2 scaling, add bias
    const float inv = 1.0f / 1024.0f;
#pragma unroll
    for (int mf = 0; mf < 2; mf++) {
        int r0 = bm + wm * 32 + mf * 16 + (lane >> 2);
#pragma unroll
        for (int nf = 0; nf < 4; nf++) {
            int cc = bn + wn * 32 + nf * 8 + (lane & 3) * 2;
            float2 b2 = *(const float2*)&bias[cc];
            float2 v0 = make_float2(acc[mf][nf][0] * inv + b2.x,
                                    acc[mf][nf][1] * inv + b2.y);
            float2 v1 = make_float2(acc[mf][nf][2] * inv + b2.x,
                                    acc[mf][nf][3] * inv + b2.y);
            *(float2*)&C[(size_t)r0 * EMB + cc]       = v0;
            *(float2*)&C[(size_t)(r0 + 8) * EMB + cc] = v1;
        }
    }
}

// ---------------------------------------------------------------------------
extern "C" void kernel_launch(void* const* d_in, const int* in_sizes, int n_in,
                              void* d_out, int out_size) {
    const float* x      = (const float*)d_in[0];  // [16,2048,8]
    const float* params = (const float*)d_in[1];  // [8,3]
    const float* W1     = (const float*)d_in[2];  // [2048,8]
    const float* b1     = (const float*)d_in[3];  // [2048]
    const float* W2     = (const float*)d_in[4];  // [512,2048]
    const float* b2     = (const float*)d_in[5];  // [512]
    float* out = (float*)d_out;                   // [16,2048,512]

    w_split_kernel<<<(EMB * (FFN / 2)) / 256, 256>>>(W2);
    ev_kernel<<<NROWS / 256, 256>>>(x, params);
    h_half_kernel<<<dim3(FFN / 512, NROWS / HROWS), 256>>>(W1, b1);
    mma_gemm<<<dim3(EMB / BN, NROWS / BM), 256>>>(b2, out);
}

// round 7
// speedup vs baseline: 4.0047x; 1.1346x over previous
#include <cuda_runtime.h>
#include <cuda_fp16.h>
#include <math.h>
#include <stdint.h>

#define NROWS 32768      // B*S
#define FFN   2048
#define EMB   512

// ---------------- scratch ---------------------------------------------------
__device__ float  g_EV[NROWS * 8];                 // 1 MB
__device__ __half g_H[(size_t)NROWS * FFN];        // 128 MB (fp16 of H)
__device__ __half g_Wh[EMB * FFN];                 // 2 MB  (fp16 hi of 1024*W2)
__device__ __half g_Wl[EMB * FFN];                 // 2 MB  (fp16 lo of 1024*W2)

// ---------------------------------------------------------------------------
// Kernel 1: quantum circuit collapsed to closed form (verified R1/R2).
// ---------------------------------------------------------------------------
__global__ void ev_kernel(const float* __restrict__ x,
                          const float* __restrict__ params) {
    int row = blockIdx.x * blockDim.x + threadIdx.x;
    if (row >= NROWS) return;
    float z[8];
#pragma unroll
    for (int i = 0; i < 8; i++) {
        float a = params[i * 3 + 0];
        float b = params[i * 3 + 1];
        float c = params[i * 3 + 2];
        float sa, ca, sb, cb, sc, cc;
        sincosf(a, &sa, &ca);
        sincosf(b, &sb, &cb);
        sincosf(c, &sc, &cc);
        float Acoef = ca * cc + sa * sb * sc;
        float Ccoef = cb * sc;
        float sx, cx;
        sincosf(x[row * 8 + i], &sx, &cx);
        z[i] = Acoef * cx - Ccoef * sx;
    }
    float ev[8];
    float pre = z[0];
#pragma unroll
    for (int k = 1; k < 8; k++) { pre *= z[k]; ev[k] = pre; }
    float suf = 1.0f;
#pragma unroll
    for (int k = 7; k >= 1; k--) suf *= z[k];
    ev[0] = suf;
    float4* out = (float4*)&g_EV[row * 8];
    out[0] = make_float4(ev[0], ev[1], ev[2], ev[3]);
    out[1] = make_float4(ev[4], ev[5], ev[6], ev[7]);
}

// ---------------------------------------------------------------------------
// Kernel 2: H = relu(EV @ W1^T + b1) -> fp16.  (R6-proven: col-owning threads)
// ---------------------------------------------------------------------------
#define HROWS 64
__global__ void __launch_bounds__(256)
h_half_kernel(const float* __restrict__ W1, const float* __restrict__ b1) {
    int c0 = blockIdx.x * 512 + threadIdx.x * 2;
    int r0 = blockIdx.y * HROWS;
    float4 wa0 = *(const float4*)&W1[c0 * 8];
    float4 wa1 = *(const float4*)&W1[c0 * 8 + 4];
    float4 wb0 = *(const float4*)&W1[(c0 + 1) * 8];
    float4 wb1 = *(const float4*)&W1[(c0 + 1) * 8 + 4];
    float ba = b1[c0], bb = b1[c0 + 1];
#pragma unroll 4
    for (int r = r0; r < r0 + HROWS; r++) {
        float4 e0 = *(const float4*)&g_EV[r * 8];
        float4 e1 = *(const float4*)&g_EV[r * 8 + 4];
        float ha = ba
                 + e0.x * wa0.x + e0.y * wa0.y + e0.z * wa0.z + e0.w * wa0.w
                 + e1.x * wa1.x + e1.y * wa1.y + e1.z * wa1.z + e1.w * wa1.w;
        float hb = bb
                 + e0.x * wb0.x + e0.y * wb0.y + e0.z * wb0.z + e0.w * wb0.w
                 + e1.x * wb1.x + e1.y * wb1.y + e1.z * wb1.z + e1.w * wb1.w;
        __half2 hv = __floats2half2_rn(fmaxf(ha, 0.0f), fmaxf(hb, 0.0f));
        *(__half2*)&g_H[(size_t)r * FFN + c0] = hv;
    }
}

// ---------------------------------------------------------------------------
// Kernel 3: split 1024*W2 into fp16 hi/lo
// ---------------------------------------------------------------------------
__global__ void w_split_kernel(const float* __restrict__ W2) {
    int idx = blockIdx.x * blockDim.x + threadIdx.x;
    float2 v = ((const float2*)W2)[idx];
    float v0 = v.x * 1024.0f, v1 = v.y * 1024.0f;
    __half h0 = __float2half(v0);
    __half h1 = __float2half(v1);
    __half l0 = __float2half(v0 - __half2float(h0));
    __half l1 = __float2half(v1 - __half2float(h1));
    ((__half2*)g_Wh)[idx] = __halves2half2(h0, h1);
    ((__half2*)g_Wl)[idx] = __halves2half2(l0, l1);
}

// ---------------------------------------------------------------------------
// Kernel 4: OUT = H @ W2^T + b2, mma.sync fp16 2-pass.
// CTA 128x64x32, 4 warps (2x2, warp tile 64x32), 3-stage cp.async,
// 48KB static smem, 4 CTAs/SM, single barrier per stage.
// ---------------------------------------------------------------------------
#define BM 128
#define BN 64
#define BK 32
#define NT (FFN / BK)             // 64
#define STG 16384                 // A 0 (8192), Bh 8192 (4096), Bl 12288 (4096)

#define CP16(dst, src) \
    asm volatile("cp.async.cg.shared.global [%0], [%1], 16;\n" :: "r"(dst), "l"(src))

__device__ __forceinline__ void ldsm4(unsigned* r, unsigned a) {
    asm volatile("ldmatrix.sync.aligned.m8n8.x4.shared.b16 {%0,%1,%2,%3}, [%4];"
                 : "=r"(r[0]), "=r"(r[1]), "=r"(r[2]), "=r"(r[3]) : "r"(a));
}

__device__ __forceinline__ void mma16816(float* c, const unsigned* a, const unsigned* b) {
    asm volatile("mma.sync.aligned.m16n8k16.row.col.f32.f16.f16.f32 "
                 "{%0,%1,%2,%3}, {%4,%5,%6,%7}, {%8,%9}, {%0,%1,%2,%3};"
                 : "+f"(c[0]), "+f"(c[1]), "+f"(c[2]), "+f"(c[3])
                 : "r"(a[0]), "r"(a[1]), "r"(a[2]), "r"(a[3]), "r"(b[0]), "r"(b[1]));
}

__device__ __forceinline__ unsigned swz(int row, int ch) {  // 64B rows, 16B chunks
    return (unsigned)(row * 64 + ((ch ^ ((row >> 1) & 3)) << 4));
}

__device__ __forceinline__ void load_stage(unsigned st, int bm, int bn, int tid, int k0) {
#pragma unroll
    for (int i = 0; i < 4; i++) {               // A: 512 chunks of 16B
        int id = tid + (i << 7);
        int r = id >> 2, c = id & 3;
        size_t g = (size_t)(bm + r) * FFN + k0 + c * 8;
        CP16(st + swz(r, c), g_H + g);
    }
#pragma unroll
    for (int i = 0; i < 2; i++) {               // B: 256 chunks each hi/lo
        int id = tid + (i << 7);
        int r = id >> 2, c = id & 3;
        unsigned so = swz(r, c);
        size_t g = (size_t)(bn + r) * FFN + k0 + c * 8;
        CP16(st + 8192 + so,  g_Wh + g);
        CP16(st + 12288 + so, g_Wl + g);
    }
}

__global__ void __launch_bounds__(128, 4)
mma_gemm(const float* __restrict__ bias, float* __restrict__ C) {
    __shared__ __align__(128) unsigned char smem[3 * STG];
    const int tid  = threadIdx.x;
    const int warp = tid >> 5, lane = tid & 31;
    const int wm = warp & 1;                 // 2 m-groups of 64 rows
    const int wn = warp >> 1;                // 2 n-groups of 32 cols
    const int bm = blockIdx.y * BM, bn = blockIdx.x * BN;
    const unsigned sbase = (unsigned)__cvta_generic_to_shared(smem);

    float acc[4][4][4];                      // [mf][nf][frag]
#pragma unroll
    for (int i = 0; i < 4; i++)
#pragma unroll
        for (int j = 0; j < 4; j++)
#pragma unroll
            for (int k = 0; k < 4; k++) acc[i][j][k] = 0.0f;

    load_stage(sbase,       bm, bn, tid, 0);
    asm volatile("cp.async.commit_group;\n");
    load_stage(sbase + STG, bm, bn, tid, BK);
    asm volatile("cp.async.commit_group;\n");

    for (int t = 0; t < NT; t++) {
        if (t + 1 < NT) asm volatile("cp.async.wait_group 1;\n" ::: "memory");
        else            asm volatile("cp.async.wait_group 0;\n" ::: "memory");
        __syncthreads();          // single barrier per stage (3-stage ring)

        if (t + 2 < NT) {
            load_stage(sbase + ((t + 2) % 3) * STG, bm, bn, tid, (t + 2) * BK);
            asm volatile("cp.async.commit_group;\n");
        }

        unsigned st = sbase + (t % 3) * STG;
#pragma unroll
        for (int kk = 0; kk < 2; kk++) {
            unsigned ah[4][4], bh[2][4], bl[2][4];
#pragma unroll
            for (int mf = 0; mf < 4; mf++) {     // A frags: m64 x k16
                int r  = wm * 64 + mf * 16 + (lane & 15);
                int ch = kk * 2 + (lane >> 4);
                ldsm4(ah[mf], st + swz(r, ch));
            }
#pragma unroll
            for (int nb = 0; nb < 2; nb++) {     // B frags: n32 hi+lo
                int n  = wn * 32 + nb * 16 + (lane & 7) + ((lane >> 4) & 1) * 8;
                int ch = kk * 2 + ((lane >> 3) & 1);
                unsigned a = st + 8192 + swz(n, ch);
                ldsm4(bh[nb], a);
                ldsm4(bl[nb], a + 4096);
            }
#pragma unroll
            for (int mf = 0; mf < 4; mf++)
#pragma unroll
                for (int nf = 0; nf < 4; nf++) {
                    const unsigned* bhp = &bh[nf >> 1][(nf & 1) * 2];
                    const unsigned* blp = &bl[nf >> 1][(nf & 1) * 2];
                    mma16816(acc[mf][nf], ah[mf], bhp);   // Ah*Bh
                    mma16816(acc[mf][nf], ah[mf], blp);   // Ah*Bl
                }
        }
    }

    // epilogue: undo the 1024x W2 scaling, add bias
    const float inv = 1.0f / 1024.0f;
#pragma unroll
    for (int mf = 0; mf < 4; mf++) {
        int r0 = bm + wm * 64 + mf * 16 + (lane >> 2);
#pragma unroll
        for (int nf = 0; nf < 4; nf++) {
            int cc = bn + wn * 32 + nf * 8 + (lane & 3) * 2;
            float2 b2 = *(const float2*)&bias[cc];
            float2 v0 = make_float2(acc[mf][nf][0] * inv + b2.x,
                                    acc[mf][nf][1] * inv + b2.y);
            float2 v1 = make_float2(acc[mf][nf][2] * inv + b2.x,
                                    acc[mf][nf][3] * inv + b2.y);
            *(float2*)&C[(size_t)r0 * EMB + cc]       = v0;
            *(float2*)&C[(size_t)(r0 + 8) * EMB + cc] = v1;
        }
    }
}

// ---------------------------------------------------------------------------
extern "C" void kernel_launch(void* const* d_in, const int* in_sizes, int n_in,
                              void* d_out, int out_size) {
    const float* x      = (const float*)d_in[0];  // [16,2048,8]
    const float* params = (const float*)d_in[1];  // [8,3]
    const float* W1     = (const float*)d_in[2];  // [2048,8]
    const float* b1     = (const float*)d_in[3];  // [2048]
    const float* W2     = (const float*)d_in[4];  // [512,2048]
    const float* b2     = (const float*)d_in[5];  // [512]
    float* out = (float*)d_out;                   // [16,2048,512]

    w_split_kernel<<<(EMB * (FFN / 2)) / 256, 256>>>(W2);
    ev_kernel<<<NROWS / 256, 256>>>(x, params);
    h_half_kernel<<<dim3(FFN / 512, NROWS / HROWS), 256>>>(W1, b1);
    mma_gemm<<<dim3(EMB / BN, NROWS / BM), 128>>>(b2, out);
}